// round 2
// baseline (speedup 1.0000x reference)
#include <cuda_runtime.h>
#include <cstdint>

#define T_STEPS 784
#define BATCH   512
#define HID     200
#define G4      800
#define NCTA    128
#define THREADS 256
#define UNITS_PER 25
#define BT_ROWS 64

// ---------------- device global scratch (static, no allocation) ----------------
__device__ float g_u[2][G4];
__device__ float g_v[2][G4];
__device__ float g_h[2][2][BATCH][HID];     // [parity][dir][b][j]
__device__ float g_hbar[2][T_STEPS][HID];   // batch SUMS of h
__device__ unsigned int g_bar_count;
__device__ volatile unsigned int g_bar_gen;

// ---------------- smem layout (bytes) ----------------
#define BP_OFF 0          // uint2 [25][16][32]   102400
#define AP_OFF 102400     // uint  [25][4][32][4]  51200
#define GB_OFF 153600     // float [64][132]       33792
#define CB_OFF 187392     // float [64][26]         6656
#define HS_OFF 194048     // float [64][26]         6656
#define SU_OFF 200704     // float [128]             512
#define SV_OFF 201216     // float [128]             512
#define XS_OFF 201728     // float [64]              256
#define PS_OFF 201984     // float [200]             800
#define SMEM_BYTES 202784

__device__ __forceinline__ uint32_t f2tf(float x) {
    uint32_t r;
    asm("cvt.rna.tf32.f32 %0, %1;" : "=r"(r) : "f"(x));
    return r;
}
__device__ __forceinline__ float sigf(float x) {
    return __fdividef(1.f, 1.f + __expf(-x));
}
__device__ __forceinline__ float tanh_fast(float x) {
    return 2.f * sigf(2.f * x) - 1.f;
}

// ---------------- precompute: rank-1 input-gate vectors + zeroing ----------------
__global__ void precompute_kernel(const float* __restrict__ W_in,
                                  const float* __restrict__ b_in,
                                  const float* __restrict__ Wih_f,
                                  const float* __restrict__ b_f,
                                  const float* __restrict__ Wih_b,
                                  const float* __restrict__ b_b) {
    int idx = blockIdx.x * blockDim.x + threadIdx.x;
    int nth = gridDim.x * blockDim.x;
    if (idx == 0) { g_bar_count = 0; g_bar_gen = 0; }
    for (int i = idx; i < 2 * G4; i += nth) {
        int dir = i / G4, row = i % G4;
        const float* Wih = dir ? Wih_b : Wih_f;
        const float* bb  = dir ? b_b   : b_f;
        float su = 0.f, sv = 0.f;
        for (int k = 0; k < HID; k++) {
            float w = Wih[row * HID + k];
            su += w * W_in[k];
            sv += w * b_in[k];
        }
        g_u[dir][row] = su;
        g_v[dir][row] = sv + bb[row];
    }
    float* hb = &g_hbar[0][0][0];
    for (int i = idx; i < 2 * T_STEPS * HID; i += nth) hb[i] = 0.f;
    float* hh = &g_h[0][0][0][0];
    for (int i = idx; i < 2 * 2 * BATCH * HID; i += nth) hh[i] = 0.f;
}

// ---------------- persistent recurrence kernel ----------------
__global__ void __launch_bounds__(THREADS, 1)
lstm_kernel(const float* __restrict__ x,
            const float* __restrict__ Whh_f,
            const float* __restrict__ Whh_b) {
    extern __shared__ unsigned char smem_raw[];
    uint2*    Bp   = (uint2*)   (smem_raw + BP_OFF);
    uint32_t* Ap   = (uint32_t*)(smem_raw + AP_OFF);
    float*    Gbuf = (float*)   (smem_raw + GB_OFF);
    float*    cbuf = (float*)   (smem_raw + CB_OFF);
    float*    hsb  = (float*)   (smem_raw + HS_OFF);
    float*    su   = (float*)   (smem_raw + SU_OFF);
    float*    sv   = (float*)   (smem_raw + SV_OFF);
    float*    xs   = (float*)   (smem_raw + XS_OFF);
    float*    psum = (float*)   (smem_raw + PS_OFF);

    const int tid = threadIdx.x;
    const int cta = blockIdx.x;
    const int dir = cta >> 6;
    const int bt  = (cta >> 3) & 7;
    const int ut  = cta & 7;
    const int j0  = ut * UNITS_PER;
    const float* Whh = dir ? Whh_b : Whh_f;

    // ---- prologue: per-CTA gate-input vectors, c=0, Whh fragment layout ----
    for (int i = tid; i < 128; i += THREADS) {
        int gamma = i >> 5, u = i & 31;
        float uu = 0.f, vv = 0.f;
        if (u < UNITS_PER) {
            int row = gamma * HID + j0 + u;
            uu = g_u[dir][row];
            vv = g_v[dir][row];
        }
        su[i] = uu; sv[i] = vv;
    }
    for (int i = tid; i < BT_ROWS * 26; i += THREADS) cbuf[i] = 0.f;
    // Bp[(kc*16+nsub)*32+lane] = {Whh[row(n)][kc*8+tig], Whh[row(n)][kc*8+tig+4]} (tf32)
    for (int i = tid; i < 25 * 16 * 32; i += THREADS) {
        int kc = i / 512;
        int r  = i % 512;
        int nsub = r >> 5;
        int lane = r & 31;
        int g = lane >> 2, tig = lane & 3;
        int n = nsub * 8 + g;
        int gamma = n >> 5, u = n & 31;
        float b0v = 0.f, b1v = 0.f;
        if (u < UNITS_PER) {
            int row = gamma * HID + j0 + u;
            int k0 = kc * 8 + tig;
            b0v = Whh[row * HID + k0];
            b1v = Whh[row * HID + k0 + 4];
        }
        Bp[i] = make_uint2(f2tf(b0v), f2tf(b1v));
    }
    __syncthreads();

    const int warp = tid >> 5;
    const int lane = tid & 31;
    const int mt = warp & 3;   // 16-row tile within 64
    const int nh = warp >> 2;  // 64-col half within 128

    for (int s = 0; s < T_STEPS; s++) {
        const int p = s & 1;
        const int t = dir ? (T_STEPS - 1 - s) : s;
        const float* hin  = &g_h[p][dir][0][0];
        float*       hout = &g_h[p ^ 1][dir][0][0];

        // ---- Phase A: stage h tile into MMA A-fragment layout (tf32) ----
        for (int i = tid; i < BT_ROWS * HID; i += THREADS) {
            int b = i / HID;
            int k = i - b * HID;
            float v = hin[(bt * BT_ROWS + b) * HID + k];
            int kc = k >> 3, kk = k & 7;
            int tg = kk & 3, half = kk >> 2;
            int mtt = b >> 4, rr = b & 15;
            int gg = rr & 7, hi = rr >> 3;
            int ln = (gg << 2) | tg;
            int comp = (half << 1) | hi;
            Ap[(((kc * 4 + mtt) << 5) | ln) * 4 + comp] = f2tf(v);
        }
        if (tid < BT_ROWS) xs[tid] = x[t * BATCH + bt * BT_ROWS + tid];
        __syncthreads();

        // ---- Phase B: G_raw = h @ Whh_slice^T via m16n8k8 tf32 MMA ----
        float acc[8][4];
        #pragma unroll
        for (int j = 0; j < 8; j++) {
            acc[j][0] = acc[j][1] = acc[j][2] = acc[j][3] = 0.f;
        }
        const uint4* ApV = (const uint4*)Ap;
        #pragma unroll 5
        for (int kc = 0; kc < 25; kc++) {
            uint4 a = ApV[(kc * 4 + mt) * 32 + lane];
            uint2 bb[8];
            #pragma unroll
            for (int j = 0; j < 8; j++)
                bb[j] = Bp[(kc * 16 + nh * 8 + j) * 32 + lane];
            #pragma unroll
            for (int j = 0; j < 8; j++) {
                asm volatile(
                    "mma.sync.aligned.m16n8k8.row.col.f32.tf32.tf32.f32 "
                    "{%0,%1,%2,%3}, {%4,%5,%6,%7}, {%8,%9}, {%0,%1,%2,%3};\n"
                    : "+f"(acc[j][0]), "+f"(acc[j][1]), "+f"(acc[j][2]), "+f"(acc[j][3])
                    : "r"(a.x), "r"(a.y), "r"(a.z), "r"(a.w),
                      "r"(bb[j].x), "r"(bb[j].y));
            }
        }
        // ---- Phase C: spill accumulators to smem ----
        {
            int g = lane >> 2, tg = lane & 3;
            int row0 = mt * 16 + g;
            #pragma unroll
            for (int j = 0; j < 8; j++) {
                int col = (nh * 8 + j) * 8 + tg * 2;
                *(float2*)&Gbuf[row0 * 132 + col]       = make_float2(acc[j][0], acc[j][1]);
                *(float2*)&Gbuf[(row0 + 8) * 132 + col] = make_float2(acc[j][2], acc[j][3]);
            }
        }
        __syncthreads();

        // ---- Phase D: gates + state update ----
        for (int i = tid; i < BT_ROWS * UNITS_PER; i += THREADS) {
            int b = i / UNITS_PER;
            int u = i - b * UNITS_PER;
            float xi = xs[b];
            const float* gr = &Gbuf[b * 132];
            float gi = gr[u]      + xi * su[u]      + sv[u];
            float gf = gr[32 + u] + xi * su[32 + u] + sv[32 + u];
            float gg = gr[64 + u] + xi * su[64 + u] + sv[64 + u];
            float go = gr[96 + u] + xi * su[96 + u] + sv[96 + u];
            float cold = cbuf[b * 26 + u];
            float cn = sigf(gf) * cold + sigf(gi) * tanh_fast(gg);
            cbuf[b * 26 + u] = cn;
            float h = sigf(go) * tanh_fast(cn);
            hout[(bt * BT_ROWS + b) * HID + j0 + u] = h;
            hsb[b * 26 + u] = h;
        }
        __syncthreads();

        // ---- Phase E: batch-partial sums -> global hbar ----
        if (tid < 200) {
            int u = tid >> 3;
            int seg = tid & 7;
            float sum = 0.f;
            #pragma unroll
            for (int b = 0; b < 8; b++) sum += hsb[(seg * 8 + b) * 26 + u];
            psum[tid] = sum;
        }
        __syncthreads();
        if (tid < UNITS_PER) {
            float sum = 0.f;
            #pragma unroll
            for (int k = 0; k < 8; k++) sum += psum[tid * 8 + k];
            atomicAdd(&g_hbar[dir][t][j0 + tid], sum);
        }

        // ---- grid barrier (sense-reversing, all 128 CTAs resident) ----
        __syncthreads();
        if (tid == 0) {
            unsigned int gen = g_bar_gen;
            __threadfence();
            unsigned int old = atomicAdd(&g_bar_count, 1u);
            if (old == NCTA - 1) {
                g_bar_count = 0;
                __threadfence();
                g_bar_gen = gen + 1;
            } else {
                while (g_bar_gen == gen) { __nanosleep(64); }
            }
            __threadfence();
        }
        __syncthreads();
    }
}

// ---------------- final linear head on batch-mean h ----------------
__global__ void finalize_kernel(const float* __restrict__ W_fc,
                                const float* __restrict__ b_fc,
                                float* __restrict__ out) {
    int i = blockIdx.x * blockDim.x + threadIdx.x;
    if (i >= T_STEPS * 10) return;
    int t = i / 10, o = i % 10;
    const float* wf = &W_fc[o * (2 * HID)];
    float acc = 0.f;
    for (int j = 0; j < HID; j++) acc += wf[j] * g_hbar[0][t][j];
    for (int j = 0; j < HID; j++) acc += wf[HID + j] * g_hbar[1][t][j];
    out[i] = b_fc[o] + acc * (1.f / 512.f);
}

extern "C" void kernel_launch(void* const* d_in, const int* in_sizes, int n_in,
                              void* d_out, int out_size) {
    const float* x     = (const float*)d_in[0];
    const float* W_in  = (const float*)d_in[1];
    const float* b_in  = (const float*)d_in[2];
    const float* Wih_f = (const float*)d_in[3];
    const float* Whh_f = (const float*)d_in[4];
    const float* b_f   = (const float*)d_in[5];
    const float* Wih_b = (const float*)d_in[6];
    const float* Whh_b = (const float*)d_in[7];
    const float* b_b   = (const float*)d_in[8];
    const float* W_fc  = (const float*)d_in[9];
    const float* b_fc  = (const float*)d_in[10];
    float* out = (float*)d_out;

    cudaFuncSetAttribute(lstm_kernel,
                         cudaFuncAttributeMaxDynamicSharedMemorySize, SMEM_BYTES);

    precompute_kernel<<<32, 256>>>(W_in, b_in, Wih_f, b_f, Wih_b, b_b);
    lstm_kernel<<<NCTA, THREADS, SMEM_BYTES>>>(x, Whh_f, Whh_b);
    finalize_kernel<<<(T_STEPS * 10 + 255) / 256, 256>>>(W_fc, b_fc, out);
}

// round 5
// speedup vs baseline: 1.2007x; 1.2007x over previous
#include <cuda_runtime.h>
#include <cstdint>

#define T_STEPS 784
#define BATCH   512
#define HID     200
#define G4      800
#define NCTA    128
#define THREADS 256
#define UNITS_PER 25
#define BT_ROWS 64
#define FRAG_U32 12800   // uints per (parity,dir,bt) A-fragment block

// ---------------- device global scratch (static, no allocation) ----------------
__device__ float g_u[2][G4];
__device__ float g_v[2][G4];
__device__ uint32_t g_hfrag[2][2][8][FRAG_U32];   // [parity][dir][bt][frag]
__device__ float g_hpart[2][8][T_STEPS][HID];     // per-(dir,bt) batch partial sums

// ---------------- smem layout (bytes) ----------------
#define BP_OFF 0          // uint2 [25][16][32]   102400
#define GB_OFF 102400     // float [64][132]       33792
#define CB_OFF 136192     // float [64][26]         6656
#define HS_OFF 142848     // float [64][26]         6656
#define SU_OFF 149504     // float [128]             512
#define SV_OFF 150016     // float [128]             512
#define XS_OFF 150528     // float [64]              256
#define PS_OFF 150784     // float [200]             800
#define SMEM_BYTES 151584

__device__ __forceinline__ uint32_t f2tf(float x) {
    uint32_t r;
    asm("cvt.rna.tf32.f32 %0, %1;" : "=r"(r) : "f"(x));
    return r;
}
__device__ __forceinline__ float tanha(float x) {
    float r;
    asm("tanh.approx.f32 %0, %1;" : "=f"(r) : "f"(x));
    return r;
}
__device__ __forceinline__ float sigf(float x) {
    return fmaf(0.5f, tanha(0.5f * x), 0.5f);
}
__device__ __forceinline__ uint4 ldg_cg_v4(const uint32_t* p) {
    uint4 v;
    asm volatile("ld.global.cg.v4.u32 {%0,%1,%2,%3}, [%4];"
                 : "=r"(v.x), "=r"(v.y), "=r"(v.z), "=r"(v.w) : "l"(p));
    return v;
}

// ---------------- precompute: rank-1 input-gate vectors + zeroing ----------------
__global__ void precompute_kernel(const float* __restrict__ W_in,
                                  const float* __restrict__ b_in,
                                  const float* __restrict__ Wih_f,
                                  const float* __restrict__ b_f,
                                  const float* __restrict__ Wih_b,
                                  const float* __restrict__ b_b) {
    int idx = blockIdx.x * blockDim.x + threadIdx.x;
    int nth = gridDim.x * blockDim.x;
    for (int i = idx; i < 2 * G4; i += nth) {
        int dir = i / G4, row = i % G4;
        const float* Wih = dir ? Wih_b : Wih_f;
        const float* bb  = dir ? b_b   : b_f;
        float su = 0.f, sv = 0.f;
        for (int k = 0; k < HID; k++) {
            float w = Wih[row * HID + k];
            su += w * W_in[k];
            sv += w * b_in[k];
        }
        g_u[dir][row] = su;
        g_v[dir][row] = sv + bb[row];
    }
    uint32_t* hf = &g_hfrag[0][0][0][0];
    for (int i = idx; i < 2 * 2 * 8 * FRAG_U32; i += nth) hf[i] = 0u;
}

// ---------------- persistent recurrence kernel: 16 clusters of 8 CTAs ----------------
__global__ void __launch_bounds__(THREADS, 1) __cluster_dims__(8, 1, 1)
lstm_kernel(const float* __restrict__ x,
            const float* __restrict__ Whh_f,
            const float* __restrict__ Whh_b) {
    extern __shared__ unsigned char smem_raw[];
    uint2* Bp   = (uint2*)(smem_raw + BP_OFF);
    float* Gbuf = (float*)(smem_raw + GB_OFF);
    float* cbuf = (float*)(smem_raw + CB_OFF);
    float* hsb  = (float*)(smem_raw + HS_OFF);
    float* su   = (float*)(smem_raw + SU_OFF);
    float* sv   = (float*)(smem_raw + SV_OFF);
    float* xs   = (float*)(smem_raw + XS_OFF);
    float* psum = (float*)(smem_raw + PS_OFF);

    const int tid = threadIdx.x;
    const int cta = blockIdx.x;
    const int dir = cta >> 6;
    const int bt  = (cta >> 3) & 7;
    const int ut  = cta & 7;
    const int j0  = ut * UNITS_PER;
    const float* Whh = dir ? Whh_b : Whh_f;

    // ---- prologue: gate vectors, c=0, Whh B-fragment layout ----
    for (int i = tid; i < 128; i += THREADS) {
        int gamma = i >> 5, u = i & 31;
        float uu = 0.f, vv = 0.f;
        if (u < UNITS_PER) {
            int row = gamma * HID + j0 + u;
            uu = g_u[dir][row];
            vv = g_v[dir][row];
        }
        su[i] = uu; sv[i] = vv;
    }
    for (int i = tid; i < BT_ROWS * 26; i += THREADS) cbuf[i] = 0.f;
    for (int i = tid; i < 25 * 16 * 32; i += THREADS) {
        int kc = i / 512;
        int r  = i % 512;
        int nsub = r >> 5;
        int lane = r & 31;
        int g = lane >> 2, tig = lane & 3;
        int n = nsub * 8 + g;
        int gamma = n >> 5, u = n & 31;
        float b0v = 0.f, b1v = 0.f;
        if (u < UNITS_PER) {
            int row = gamma * HID + j0 + u;
            int k0 = kc * 8 + tig;
            b0v = Whh[row * HID + k0];
            b1v = Whh[row * HID + k0 + 4];
        }
        Bp[i] = make_uint2(f2tf(b0v), f2tf(b1v));
    }
    __syncthreads();
    // cluster-wide rendezvous before the first step's cross-CTA reads
    asm volatile("barrier.cluster.arrive.aligned;" ::: "memory");
    asm volatile("barrier.cluster.wait.aligned;" ::: "memory");

    const int warp = tid >> 5;
    const int lane = tid & 31;
    const int mt = warp & 3;   // 16-row tile within 64
    const int nh = warp >> 2;  // 64-col half within 128

    for (int s = 0; s < T_STEPS; s++) {
        const int p = s & 1;
        const int t = dir ? (T_STEPS - 1 - s) : s;
        const uint32_t* fin  = &g_hfrag[p][dir][bt][0];
        uint32_t*       fout = &g_hfrag[p ^ 1][dir][bt][0];

        if (tid < BT_ROWS) xs[tid] = x[t * BATCH + bt * BT_ROWS + tid];

        // ---- Phase B: G = h @ Whh^T, A-fragments streamed from L2 ----
        float acc[8][4];
        #pragma unroll
        for (int j = 0; j < 8; j++)
            acc[j][0] = acc[j][1] = acc[j][2] = acc[j][3] = 0.f;

        uint4 areg[4];
        #pragma unroll
        for (int i = 0; i < 4; i++)
            areg[i] = ldg_cg_v4(fin + (((i * 4 + mt) << 5) | lane) * 4);

        #pragma unroll
        for (int kc = 0; kc < 25; kc++) {
            uint4 a = areg[kc & 3];
            if (kc + 4 < 25)
                areg[kc & 3] = ldg_cg_v4(fin + ((((kc + 4) * 4 + mt) << 5) | lane) * 4);
            uint2 bb[8];
            #pragma unroll
            for (int j = 0; j < 8; j++)
                bb[j] = Bp[(kc * 16 + nh * 8 + j) * 32 + lane];
            #pragma unroll
            for (int j = 0; j < 8; j++) {
                asm volatile(
                    "mma.sync.aligned.m16n8k8.row.col.f32.tf32.tf32.f32 "
                    "{%0,%1,%2,%3}, {%4,%5,%6,%7}, {%8,%9}, {%0,%1,%2,%3};\n"
                    : "+f"(acc[j][0]), "+f"(acc[j][1]), "+f"(acc[j][2]), "+f"(acc[j][3])
                    : "r"(a.x), "r"(a.y), "r"(a.z), "r"(a.w),
                      "r"(bb[j].x), "r"(bb[j].y));
            }
        }
        // ---- Phase C: spill accumulators to smem ----
        {
            int g = lane >> 2, tg = lane & 3;
            int row0 = mt * 16 + g;
            #pragma unroll
            for (int j = 0; j < 8; j++) {
                int col = (nh * 8 + j) * 8 + tg * 2;
                *(float2*)&Gbuf[row0 * 132 + col]       = make_float2(acc[j][0], acc[j][1]);
                *(float2*)&Gbuf[(row0 + 8) * 132 + col] = make_float2(acc[j][2], acc[j][3]);
            }
        }
        __syncthreads();

        // ---- Phase D: gates + state update; write h as tf32 A-fragments ----
        for (int i = tid; i < BT_ROWS * UNITS_PER; i += THREADS) {
            int b = i / UNITS_PER;
            int u = i - b * UNITS_PER;
            float xi = xs[b];
            const float* gr = &Gbuf[b * 132];
            float gi = gr[u]      + xi * su[u]      + sv[u];
            float gf = gr[32 + u] + xi * su[32 + u] + sv[32 + u];
            float gg = gr[64 + u] + xi * su[64 + u] + sv[64 + u];
            float go = gr[96 + u] + xi * su[96 + u] + sv[96 + u];
            float cold = cbuf[b * 26 + u];
            float cn = sigf(gf) * cold + sigf(gi) * tanha(gg);
            cbuf[b * 26 + u] = cn;
            float h = sigf(go) * tanha(cn);
            hsb[b * 26 + u] = h;
            // fragment address for (b, k=j0+u)
            int k = j0 + u;
            int kc = k >> 3, kk = k & 7;
            int tg = kk & 3, half = kk >> 2;
            int mtt = b >> 4, rr = b & 15;
            int gg2 = rr & 7, hi = rr >> 3;
            int ln = (gg2 << 2) | tg;
            int comp = (half << 1) | hi;
            fout[(((kc * 4 + mtt) << 5) | ln) * 4 + comp] = f2tf(h);
        }
        __syncthreads();

        // ---- Phase E: batch partial sums -> uncontended global partials ----
        if (tid < 200) {
            int u = tid >> 3;
            int seg = tid & 7;
            float sum = 0.f;
            #pragma unroll
            for (int b = 0; b < 8; b++) sum += hsb[(seg * 8 + b) * 26 + u];
            psum[tid] = sum;
        }
        __syncthreads();
        if (tid < UNITS_PER) {
            float sum = 0.f;
            #pragma unroll
            for (int k = 0; k < 8; k++) sum += psum[tid * 8 + k];
            g_hpart[dir][bt][t][j0 + tid] = sum;
        }

        // ---- cluster barrier: arrive releases this CTA's h writes,
        //      wait acquires all 8 CTAs' writes. Doubles as CTA barrier. ----
        asm volatile("barrier.cluster.arrive.aligned;" ::: "memory");
        asm volatile("barrier.cluster.wait.aligned;" ::: "memory");
    }
}

// ---------------- finalize: reduce partials over bt, apply linear head ----------------
__global__ void finalize_kernel(const float* __restrict__ W_fc,
                                const float* __restrict__ b_fc,
                                float* __restrict__ out) {
    __shared__ float hb[2 * HID];
    int t = blockIdx.x;
    int tid = threadIdx.x;
    for (int j = tid; j < 2 * HID; j += blockDim.x) {
        int dir = j / HID, jj = j - dir * HID;
        float sum = 0.f;
        #pragma unroll
        for (int b = 0; b < 8; b++) sum += g_hpart[dir][b][t][jj];
        hb[j] = sum;
    }
    __syncthreads();
    if (tid < 10) {
        const float* wf = &W_fc[tid * (2 * HID)];
        float acc = 0.f;
        for (int j = 0; j < 2 * HID; j++) acc += wf[j] * hb[j];
        out[t * 10 + tid] = b_fc[tid] + acc * (1.f / 512.f);
    }
}

extern "C" void kernel_launch(void* const* d_in, const int* in_sizes, int n_in,
                              void* d_out, int out_size) {
    const float* x     = (const float*)d_in[0];
    const float* W_in  = (const float*)d_in[1];
    const float* b_in  = (const float*)d_in[2];
    const float* Wih_f = (const float*)d_in[3];
    const float* Whh_f = (const float*)d_in[4];
    const float* b_f   = (const float*)d_in[5];
    const float* Wih_b = (const float*)d_in[6];
    const float* Whh_b = (const float*)d_in[7];
    const float* b_b   = (const float*)d_in[8];
    const float* W_fc  = (const float*)d_in[9];
    const float* b_fc  = (const float*)d_in[10];
    float* out = (float*)d_out;

    cudaFuncSetAttribute(lstm_kernel,
                         cudaFuncAttributeMaxDynamicSharedMemorySize, SMEM_BYTES);

    precompute_kernel<<<32, 256>>>(W_in, b_in, Wih_f, b_f, Wih_b, b_b);
    lstm_kernel<<<NCTA, THREADS, SMEM_BYTES>>>(x, Whh_f, Whh_b);
    finalize_kernel<<<T_STEPS, 256>>>(W_fc, b_fc, out);
}

// round 6
// speedup vs baseline: 2.2259x; 1.8539x over previous
#include <cuda_runtime.h>
#include <cuda_fp16.h>
#include <cstdint>

#define T_STEPS 784
#define BATCH   512
#define HID     200
#define G4      800
#define NCTA    128
#define THREADS 256
#define UNITS_PER 25
#define BT_ROWS 64
#define KC_N    13              // ceil(200/16) k-chunks of 16
#define FRAG_U32 (KC_N*4*32*4)  // 6656 uint32 words per (parity,dir,bt) block

// ---------------- device global scratch (static, no allocation) ----------------
__device__ float g_u[2][G4];
__device__ float g_v[2][G4];
__device__ uint32_t g_hfrag[2][2][8][FRAG_U32];   // fp16x2 A-fragment words
__device__ float g_hpart[2][8][T_STEPS][HID];     // per-(dir,bt) batch partial sums

// ---------------- smem layout (bytes) ----------------
#define BP_OFF 0          // uint2 [13][16][32]    53248
#define GB_OFF 53248      // float [64][132]       33792
#define CB_OFF 87040      // float [64][26]         6656
#define HS_OFF 93696      // float [64][26]         6656
#define SU_OFF 100352     // float [128]             512
#define SV_OFF 100864     // float [128]             512
#define XS_OFF 101376     // float [64]              256
#define PS_OFF 101632     // float [200]             800
#define SMEM_BYTES 102432

__device__ __forceinline__ float tanha(float x) {
    float r;
    asm("tanh.approx.f32 %0, %1;" : "=f"(r) : "f"(x));
    return r;
}
__device__ __forceinline__ float sigf(float x) {
    return fmaf(0.5f, tanha(0.5f * x), 0.5f);
}
__device__ __forceinline__ uint32_t pack_h2(float lo, float hi) {
    __half2 h = __floats2half2_rn(lo, hi);
    return *(uint32_t*)&h;
}
__device__ __forceinline__ uint4 ldg_cg_v4(const uint32_t* p) {
    uint4 v;
    asm volatile("ld.global.cg.v4.u32 {%0,%1,%2,%3}, [%4];"
                 : "=r"(v.x), "=r"(v.y), "=r"(v.z), "=r"(v.w) : "l"(p));
    return v;
}

// ---------------- precompute: rank-1 input-gate vectors + zeroing ----------------
__global__ void precompute_kernel(const float* __restrict__ W_in,
                                  const float* __restrict__ b_in,
                                  const float* __restrict__ Wih_f,
                                  const float* __restrict__ b_f,
                                  const float* __restrict__ Wih_b,
                                  const float* __restrict__ b_b) {
    int idx = blockIdx.x * blockDim.x + threadIdx.x;
    int nth = gridDim.x * blockDim.x;
    for (int i = idx; i < 2 * G4; i += nth) {
        int dir = i / G4, row = i % G4;
        const float* Wih = dir ? Wih_b : Wih_f;
        const float* bb  = dir ? b_b   : b_f;
        float su = 0.f, sv = 0.f;
        for (int k = 0; k < HID; k++) {
            float w = Wih[row * HID + k];
            su += w * W_in[k];
            sv += w * b_in[k];
        }
        g_u[dir][row] = su;
        g_v[dir][row] = sv + bb[row];
    }
    uint32_t* hf = &g_hfrag[0][0][0][0];
    for (int i = idx; i < 2 * 2 * 8 * FRAG_U32; i += nth) hf[i] = 0u;
}

// ---------------- persistent recurrence kernel: 16 clusters of 8 CTAs ----------------
__global__ void __launch_bounds__(THREADS, 1) __cluster_dims__(8, 1, 1)
lstm_kernel(const float* __restrict__ x,
            const float* __restrict__ Whh_f,
            const float* __restrict__ Whh_b) {
    extern __shared__ unsigned char smem_raw[];
    uint2* Bp   = (uint2*)(smem_raw + BP_OFF);
    float* Gbuf = (float*)(smem_raw + GB_OFF);
    float* cbuf = (float*)(smem_raw + CB_OFF);
    float* hsb  = (float*)(smem_raw + HS_OFF);
    float* su   = (float*)(smem_raw + SU_OFF);
    float* sv   = (float*)(smem_raw + SV_OFF);
    float* xs   = (float*)(smem_raw + XS_OFF);
    float* psum = (float*)(smem_raw + PS_OFF);

    const int tid = threadIdx.x;
    const int cta = blockIdx.x;
    const int dir = cta >> 6;
    const int bt  = (cta >> 3) & 7;
    const int ut  = cta & 7;
    const int j0  = ut * UNITS_PER;
    const float* Whh = dir ? Whh_b : Whh_f;

    // ---- prologue: gate vectors, c=0, Whh fp16 B-fragment layout ----
    for (int i = tid; i < 128; i += THREADS) {
        int gamma = i >> 5, u = i & 31;
        float uu = 0.f, vv = 0.f;
        if (u < UNITS_PER) {
            int row = gamma * HID + j0 + u;
            uu = g_u[dir][row];
            vv = g_v[dir][row];
        }
        su[i] = uu; sv[i] = vv;
    }
    for (int i = tid; i < BT_ROWS * 26; i += THREADS) cbuf[i] = 0.f;
    // Bp[(kc*16+nsub)*32+lane]: b0 = fp16x2{W(n,k0),W(n,k0+1)}, b1 = {W(n,k0+8),W(n,k0+9)}
    // where n = nsub*8 + (lane>>2), k0 = kc*16 + 2*(lane&3)
    for (int i = tid; i < KC_N * 16 * 32; i += THREADS) {
        int kc = i / 512;
        int r  = i % 512;
        int nsub = r >> 5;
        int lane = r & 31;
        int g = lane >> 2, tg = lane & 3;
        int n = nsub * 8 + g;
        int gamma = n >> 5, u = n & 31;
        float w0 = 0.f, w1 = 0.f, w2 = 0.f, w3 = 0.f;
        if (u < UNITS_PER) {
            int row = gamma * HID + j0 + u;
            int k0 = kc * 16 + 2 * tg;
            const float* wr = &Whh[row * HID];
            if (k0     < HID) w0 = wr[k0];
            if (k0 + 1 < HID) w1 = wr[k0 + 1];
            if (k0 + 8 < HID) w2 = wr[k0 + 8];
            if (k0 + 9 < HID) w3 = wr[k0 + 9];
        }
        Bp[i] = make_uint2(pack_h2(w0, w1), pack_h2(w2, w3));
    }
    __syncthreads();
    asm volatile("barrier.cluster.arrive.aligned;" ::: "memory");
    asm volatile("barrier.cluster.wait.aligned;" ::: "memory");

    const int warp = tid >> 5;
    const int lane = tid & 31;
    const int mt = warp & 3;   // 16-row tile within 64
    const int nh = warp >> 2;  // 64-col half within 128

    for (int s = 0; s < T_STEPS; s++) {
        const int p = s & 1;
        const int t = dir ? (T_STEPS - 1 - s) : s;
        const uint32_t* fin = &g_hfrag[p][dir][bt][0];
        unsigned short* fout = (unsigned short*)&g_hfrag[p ^ 1][dir][bt][0];

        if (tid < BT_ROWS) xs[tid] = x[t * BATCH + bt * BT_ROWS + tid];

        // ---- Phase B: G = h @ Whh^T via fp16 m16n8k16, A streamed from L2 ----
        float acc[8][4];
        #pragma unroll
        for (int j = 0; j < 8; j++)
            acc[j][0] = acc[j][1] = acc[j][2] = acc[j][3] = 0.f;

        uint4 areg[4];
        #pragma unroll
        for (int i = 0; i < 4; i++)
            areg[i] = ldg_cg_v4(fin + (((i * 4 + mt) << 5) | lane) * 4);

        #pragma unroll
        for (int kc = 0; kc < KC_N; kc++) {
            uint4 a = areg[kc & 3];
            if (kc + 4 < KC_N)
                areg[kc & 3] = ldg_cg_v4(fin + ((((kc + 4) * 4 + mt) << 5) | lane) * 4);
            uint2 bb[8];
            #pragma unroll
            for (int j = 0; j < 8; j++)
                bb[j] = Bp[(kc * 16 + nh * 8 + j) * 32 + lane];
            #pragma unroll
            for (int j = 0; j < 8; j++) {
                asm volatile(
                    "mma.sync.aligned.m16n8k16.row.col.f32.f16.f16.f32 "
                    "{%0,%1,%2,%3}, {%4,%5,%6,%7}, {%8,%9}, {%0,%1,%2,%3};\n"
                    : "+f"(acc[j][0]), "+f"(acc[j][1]), "+f"(acc[j][2]), "+f"(acc[j][3])
                    : "r"(a.x), "r"(a.y), "r"(a.z), "r"(a.w),
                      "r"(bb[j].x), "r"(bb[j].y));
            }
        }
        // ---- Phase C: spill accumulators to smem ----
        {
            int g = lane >> 2, tg = lane & 3;
            int row0 = mt * 16 + g;
            #pragma unroll
            for (int j = 0; j < 8; j++) {
                int col = (nh * 8 + j) * 8 + tg * 2;
                *(float2*)&Gbuf[row0 * 132 + col]       = make_float2(acc[j][0], acc[j][1]);
                *(float2*)&Gbuf[(row0 + 8) * 132 + col] = make_float2(acc[j][2], acc[j][3]);
            }
        }
        __syncthreads();

        // ---- Phase D: gates + state; write h as fp16 fragment halves ----
        for (int i = tid; i < BT_ROWS * UNITS_PER; i += THREADS) {
            int b = i / UNITS_PER;
            int u = i - b * UNITS_PER;
            float xi = xs[b];
            const float* gr = &Gbuf[b * 132];
            float gi = gr[u]      + xi * su[u]      + sv[u];
            float gf = gr[32 + u] + xi * su[32 + u] + sv[32 + u];
            float gg = gr[64 + u] + xi * su[64 + u] + sv[64 + u];
            float go = gr[96 + u] + xi * su[96 + u] + sv[96 + u];
            float cold = cbuf[b * 26 + u];
            float cn = sigf(gf) * cold + sigf(gi) * tanha(gg);
            cbuf[b * 26 + u] = cn;
            float h = sigf(go) * tanha(cn);
            hsb[b * 26 + u] = h;
            // fp16 fragment half address for (b, k=j0+u)
            int k = j0 + u;
            int mtt = b >> 4, g2 = b & 7, rb = (b >> 3) & 1;
            int kc = k >> 4, km = k & 15;
            int tg = (km >> 1) & 3, kb = km >> 3, half = k & 1;
            int ln = (g2 << 2) | tg;
            int reg = (kb << 1) | rb;
            int idx16 = ((((kc * 4 + mtt) << 5) | ln) * 4 + reg) * 2 + half;
            __half hh = __float2half_rn(h);
            fout[idx16] = *(unsigned short*)&hh;
        }
        __syncthreads();

        // ---- arrive (release h-frag stores), overlap Phase E with peer skew ----
        asm volatile("barrier.cluster.arrive.aligned;" ::: "memory");

        // ---- Phase E: batch partial sums -> uncontended global partials ----
        if (tid < 200) {
            int u = tid >> 3;
            int seg = tid & 7;
            float sum = 0.f;
            #pragma unroll
            for (int b = 0; b < 8; b++) sum += hsb[(seg * 8 + b) * 26 + u];
            psum[tid] = sum;
        }
        __syncthreads();
        if (tid < UNITS_PER) {
            float sum = 0.f;
            #pragma unroll
            for (int k = 0; k < 8; k++) sum += psum[tid * 8 + k];
            g_hpart[dir][bt][t][j0 + tid] = sum;
        }

        // ---- wait: acquire all 8 CTAs' h writes ----
        asm volatile("barrier.cluster.wait.aligned;" ::: "memory");
        __syncthreads();
    }
}

// ---------------- finalize: reduce partials over bt, apply linear head ----------------
__global__ void finalize_kernel(const float* __restrict__ W_fc,
                                const float* __restrict__ b_fc,
                                float* __restrict__ out) {
    __shared__ float hb[2 * HID];
    int t = blockIdx.x;
    int tid = threadIdx.x;
    for (int j = tid; j < 2 * HID; j += blockDim.x) {
        int dir = j / HID, jj = j - dir * HID;
        float sum = 0.f;
        #pragma unroll
        for (int b = 0; b < 8; b++) sum += g_hpart[dir][b][t][jj];
        hb[j] = sum;
    }
    __syncthreads();
    if (tid < 10) {
        const float* wf = &W_fc[tid * (2 * HID)];
        float acc = 0.f;
        for (int j = 0; j < 2 * HID; j++) acc += wf[j] * hb[j];
        out[t * 10 + tid] = b_fc[tid] + acc * (1.f / 512.f);
    }
}

extern "C" void kernel_launch(void* const* d_in, const int* in_sizes, int n_in,
                              void* d_out, int out_size) {
    const float* x     = (const float*)d_in[0];
    const float* W_in  = (const float*)d_in[1];
    const float* b_in  = (const float*)d_in[2];
    const float* Wih_f = (const float*)d_in[3];
    const float* Whh_f = (const float*)d_in[4];
    const float* b_f   = (const float*)d_in[5];
    const float* Wih_b = (const float*)d_in[6];
    const float* Whh_b = (const float*)d_in[7];
    const float* b_b   = (const float*)d_in[8];
    const float* W_fc  = (const float*)d_in[9];
    const float* b_fc  = (const float*)d_in[10];
    float* out = (float*)d_out;

    cudaFuncSetAttribute(lstm_kernel,
                         cudaFuncAttributeMaxDynamicSharedMemorySize, SMEM_BYTES);

    precompute_kernel<<<32, 256>>>(W_in, b_in, Wih_f, b_f, Wih_b, b_b);
    lstm_kernel<<<NCTA, THREADS, SMEM_BYTES>>>(x, Whh_f, Whh_b);
    finalize_kernel<<<T_STEPS, 256>>>(W_fc, b_fc, out);
}

// round 8
// speedup vs baseline: 2.3799x; 1.0692x over previous
#include <cuda_runtime.h>
#include <cuda_fp16.h>
#include <cstdint>

#define T_STEPS 784
#define BATCH   512
#define HID     200
#define G4      800
#define NCTA    128
#define THREADS 256
#define UNITS_PER 25
#define BT_ROWS 64
#define KC_N    13              // ceil(200/16) k-chunks of 16
#define NSUB    14              // packed N = 112 (100 real gate cols + 12 pad)
#define FRAG_U32 (KC_N*4*32*4)  // 6656 uint32 words per (parity,dir,bt) block

// ---------------- device global scratch (static, no allocation) ----------------
__device__ float g_u[2][G4];
__device__ float g_v[2][G4];
__device__ uint32_t g_hfrag[2][2][8][FRAG_U32];   // fp16x2 A-fragment words
__device__ float g_hpart[2][8][T_STEPS][HID];     // per-(dir,bt) batch partial sums

// ---------------- smem layout (bytes) ----------------
#define GSTRIDE 116
#define BP_OFF 0          // uint2 [13][14][32]    46592
#define GB_OFF 46592      // float [64][116]       29696
#define CB_OFF 76288      // float [64][26]         6656
#define HS_OFF 82944      // float [64][26]         6656
#define SU_OFF 89600      // float [100]             400
#define SV_OFF 90000      // float [100]             400
#define XS_OFF 90400      // float [64]              256
#define PS_OFF 90656      // float [200]             800
#define SMEM_BYTES 91456

__device__ __forceinline__ float tanha(float x) {
    float r;
    asm("tanh.approx.f32 %0, %1;" : "=f"(r) : "f"(x));
    return r;
}
__device__ __forceinline__ float sigf(float x) {
    return fmaf(0.5f, tanha(0.5f * x), 0.5f);
}
__device__ __forceinline__ uint32_t pack_h2(float lo, float hi) {
    __half2 h = __floats2half2_rn(lo, hi);
    return *(uint32_t*)&h;
}
__device__ __forceinline__ uint4 ldg_cg_v4(const uint32_t* p) {
    uint4 v;
    asm volatile("ld.global.cg.v4.u32 {%0,%1,%2,%3}, [%4];"
                 : "=r"(v.x), "=r"(v.y), "=r"(v.z), "=r"(v.w) : "l"(p));
    return v;
}

// ---------------- precompute: rank-1 input-gate vectors + zeroing ----------------
__global__ void precompute_kernel(const float* __restrict__ W_in,
                                  const float* __restrict__ b_in,
                                  const float* __restrict__ Wih_f,
                                  const float* __restrict__ b_f,
                                  const float* __restrict__ Wih_b,
                                  const float* __restrict__ b_b) {
    int idx = blockIdx.x * blockDim.x + threadIdx.x;
    int nth = gridDim.x * blockDim.x;
    for (int i = idx; i < 2 * G4; i += nth) {
        int dir = i / G4, row = i % G4;
        const float* Wih = dir ? Wih_b : Wih_f;
        const float* bb  = dir ? b_b   : b_f;
        float su = 0.f, sv = 0.f;
        for (int k = 0; k < HID; k++) {
            float w = Wih[row * HID + k];
            su += w * W_in[k];
            sv += w * b_in[k];
        }
        g_u[dir][row] = su;
        g_v[dir][row] = sv + bb[row];
    }
    uint32_t* hf = &g_hfrag[0][0][0][0];
    for (int i = idx; i < 2 * 2 * 8 * FRAG_U32; i += nth) hf[i] = 0u;
}

// ---------------- persistent recurrence kernel: 16 clusters of 8 CTAs ----------------
__global__ void __launch_bounds__(THREADS, 1) __cluster_dims__(8, 1, 1)
lstm_kernel(const float* __restrict__ x,
            const float* __restrict__ Whh_f,
            const float* __restrict__ Whh_b) {
    extern __shared__ unsigned char smem_raw[];
    uint2* Bp   = (uint2*)(smem_raw + BP_OFF);
    float* Gbuf = (float*)(smem_raw + GB_OFF);
    float* cbuf = (float*)(smem_raw + CB_OFF);
    float* hsb  = (float*)(smem_raw + HS_OFF);
    float* su   = (float*)(smem_raw + SU_OFF);
    float* sv   = (float*)(smem_raw + SV_OFF);
    float* xs   = (float*)(smem_raw + XS_OFF);
    float* psum = (float*)(smem_raw + PS_OFF);

    const int tid = threadIdx.x;
    const int cta = blockIdx.x;
    const int dir = cta >> 6;
    const int bt  = (cta >> 3) & 7;
    const int ut  = cta & 7;
    const int j0  = ut * UNITS_PER;
    const float* Whh = dir ? Whh_b : Whh_f;

    // ---- prologue: packed gate vectors (col = gate*25+u), c=0, Whh fp16 B-frags ----
    for (int i = tid; i < 100; i += THREADS) {
        int gate = i / 25, u = i - gate * 25;
        int row = gate * HID + j0 + u;
        su[i] = g_u[dir][row];
        sv[i] = g_v[dir][row];
    }
    for (int i = tid; i < BT_ROWS * 26; i += THREADS) cbuf[i] = 0.f;
    // Bp[(kc*14+nsub)*32+lane]: b0 = fp16x2{W(n,k0),W(n,k0+1)}, b1 = {W(n,k0+8),W(n,k0+9)}
    // packed n = nsub*8 + (lane>>2); real if n<100 -> gate=n/25, u=n%25
    for (int i = tid; i < KC_N * NSUB * 32; i += THREADS) {
        int kc = i / (NSUB * 32);
        int r  = i % (NSUB * 32);
        int nsub = r >> 5;
        int lane = r & 31;
        int g = lane >> 2, tg = lane & 3;
        int n = nsub * 8 + g;
        float w0 = 0.f, w1 = 0.f, w2 = 0.f, w3 = 0.f;
        if (n < 100) {
            int gate = n / 25, u = n - gate * 25;
            int row = gate * HID + j0 + u;
            int k0 = kc * 16 + 2 * tg;
            const float* wr = &Whh[row * HID];
            if (k0     < HID) w0 = wr[k0];
            if (k0 + 1 < HID) w1 = wr[k0 + 1];
            if (k0 + 8 < HID) w2 = wr[k0 + 8];
            if (k0 + 9 < HID) w3 = wr[k0 + 9];
        }
        Bp[i] = make_uint2(pack_h2(w0, w1), pack_h2(w2, w3));
    }
    __syncthreads();
    asm volatile("barrier.cluster.arrive.aligned;" ::: "memory");
    asm volatile("barrier.cluster.wait.aligned;" ::: "memory");

    const int warp = tid >> 5;
    const int lane = tid & 31;
    const int mt = warp & 3;   // 16-row tile within 64
    const int nh = warp >> 2;  // 56-col half (7 subtiles) within 112
    const int abase = ((mt << 5) | lane) * 4;   // word offset of mt/lane A frag, kc stride 512

    for (int s = 0; s < T_STEPS; s++) {
        const int p = s & 1;
        const int t = dir ? (T_STEPS - 1 - s) : s;
        const uint32_t* fin = &g_hfrag[p][dir][bt][0];
        unsigned short* fout = (unsigned short*)&g_hfrag[p ^ 1][dir][bt][0];

        if (tid < BT_ROWS) xs[tid] = x[t * BATCH + bt * BT_ROWS + tid];

        // ---- Phase B: load ALL A-fragments (MLP=13), then LDS+HMMA only ----
        uint4 areg[KC_N];
        #pragma unroll
        for (int kc = 0; kc < KC_N; kc++)
            areg[kc] = ldg_cg_v4(fin + abase + kc * 512);

        float acc[7][4];
        #pragma unroll
        for (int j = 0; j < 7; j++)
            acc[j][0] = acc[j][1] = acc[j][2] = acc[j][3] = 0.f;

        #pragma unroll
        for (int kc = 0; kc < KC_N; kc++) {
            uint2 bb[7];
            #pragma unroll
            for (int j = 0; j < 7; j++)
                bb[j] = Bp[(kc * NSUB + nh * 7 + j) * 32 + lane];
            #pragma unroll
            for (int j = 0; j < 7; j++) {
                asm volatile(
                    "mma.sync.aligned.m16n8k16.row.col.f32.f16.f16.f32 "
                    "{%0,%1,%2,%3}, {%4,%5,%6,%7}, {%8,%9}, {%0,%1,%2,%3};\n"
                    : "+f"(acc[j][0]), "+f"(acc[j][1]), "+f"(acc[j][2]), "+f"(acc[j][3])
                    : "r"(areg[kc].x), "r"(areg[kc].y), "r"(areg[kc].z), "r"(areg[kc].w),
                      "r"(bb[j].x), "r"(bb[j].y));
            }
        }
        // ---- Phase C: spill accumulators to smem (packed cols) ----
        {
            int g = lane >> 2, tg = lane & 3;
            int row0 = mt * 16 + g;
            #pragma unroll
            for (int j = 0; j < 7; j++) {
                int col = (nh * 7 + j) * 8 + tg * 2;
                *(float2*)&Gbuf[row0 * GSTRIDE + col]       = make_float2(acc[j][0], acc[j][1]);
                *(float2*)&Gbuf[(row0 + 8) * GSTRIDE + col] = make_float2(acc[j][2], acc[j][3]);
            }
        }
        __syncthreads();

        // ---- Phase D: gates + state; write h as fp16 fragment halves ----
        for (int i = tid; i < BT_ROWS * UNITS_PER; i += THREADS) {
            int b = i / UNITS_PER;
            int u = i - b * UNITS_PER;
            float xi = xs[b];
            const float* gr = &Gbuf[b * GSTRIDE];
            float gi = gr[u]      + xi * su[u]      + sv[u];
            float gf = gr[25 + u] + xi * su[25 + u] + sv[25 + u];
            float gg = gr[50 + u] + xi * su[50 + u] + sv[50 + u];
            float go = gr[75 + u] + xi * su[75 + u] + sv[75 + u];
            float cold = cbuf[b * 26 + u];
            float cn = sigf(gf) * cold + sigf(gi) * tanha(gg);
            cbuf[b * 26 + u] = cn;
            float h = sigf(go) * tanha(cn);
            hsb[b * 26 + u] = h;
            // fp16 fragment half address for (b, k=j0+u)
            int k = j0 + u;
            int mtt = b >> 4, g2 = b & 7, rb = (b >> 3) & 1;
            int kc = k >> 4, km = k & 15;
            int tg = (km >> 1) & 3, kb = km >> 3, half = k & 1;
            int ln = (g2 << 2) | tg;
            int reg = (kb << 1) | rb;
            int idx16 = ((((kc * 4 + mtt) << 5) | ln) * 4 + reg) * 2 + half;
            __half hh = __float2half_rn(h);
            fout[idx16] = *(unsigned short*)&hh;
        }
        __syncthreads();

        // ---- arrive (release h-frag stores), overlap Phase E with peer skew ----
        asm volatile("barrier.cluster.arrive.aligned;" ::: "memory");

        // ---- Phase E: batch partial sums -> uncontended global partials ----
        if (tid < 200) {
            int u = tid >> 3;
            int seg = tid & 7;
            float sum = 0.f;
            #pragma unroll
            for (int b = 0; b < 8; b++) sum += hsb[(seg * 8 + b) * 26 + u];
            psum[tid] = sum;
        }
        __syncthreads();
        if (tid < UNITS_PER) {
            float sum = 0.f;
            #pragma unroll
            for (int k = 0; k < 8; k++) sum += psum[tid * 8 + k];
            g_hpart[dir][bt][t][j0 + tid] = sum;
        }

        // ---- wait: acquire all 8 CTAs' h writes (no extra CTA sync needed) ----
        asm volatile("barrier.cluster.wait.aligned;" ::: "memory");
    }
}

// ---------------- finalize: reduce partials over bt, apply linear head ----------------
__global__ void finalize_kernel(const float* __restrict__ W_fc,
                                const float* __restrict__ b_fc,
                                float* __restrict__ out) {
    __shared__ float hb[2 * HID];
    int t = blockIdx.x;
    int tid = threadIdx.x;
    for (int j = tid; j < 2 * HID; j += blockDim.x) {
        int dir = j / HID, jj = j - dir * HID;
        float sum = 0.f;
        #pragma unroll
        for (int b = 0; b < 8; b++) sum += g_hpart[dir][b][t][jj];
        hb[j] = sum;
    }
    __syncthreads();
    if (tid < 10) {
        const float* wf = &W_fc[tid * (2 * HID)];
        float acc = 0.f;
        for (int j = 0; j < 2 * HID; j++) acc += wf[j] * hb[j];
        out[t * 10 + tid] = b_fc[tid] + acc * (1.f / 512.f);
    }
}

extern "C" void kernel_launch(void* const* d_in, const int* in_sizes, int n_in,
                              void* d_out, int out_size) {
    const float* x     = (const float*)d_in[0];
    const float* W_in  = (const float*)d_in[1];
    const float* b_in  = (const float*)d_in[2];
    const float* Wih_f = (const float*)d_in[3];
    const float* Whh_f = (const float*)d_in[4];
    const float* b_f   = (const float*)d_in[5];
    const float* Wih_b = (const float*)d_in[6];
    const float* Whh_b = (const float*)d_in[7];
    const float* b_b   = (const float*)d_in[8];
    const float* W_fc  = (const float*)d_in[9];
    const float* b_fc  = (const float*)d_in[10];
    float* out = (float*)d_out;

    cudaFuncSetAttribute(lstm_kernel,
                         cudaFuncAttributeMaxDynamicSharedMemorySize, SMEM_BYTES);

    precompute_kernel<<<32, 256>>>(W_in, b_in, Wih_f, b_f, Wih_b, b_b);
    lstm_kernel<<<NCTA, THREADS, SMEM_BYTES>>>(x, Whh_f, Whh_b);
    finalize_kernel<<<T_STEPS, 256>>>(W_fc, b_fc, out);
}